// round 14
// baseline (speedup 1.0000x reference)
#include <cuda_runtime.h>
#include <math.h>
#include <stdint.h>

// Problem constants
#define BB    64
#define TT    128
#define INW   128
#define HHD   512
#define NND   2048
#define WWD   64
#define OUTW  128
#define RRD   4
#define CTRL  384            // IN + R*W
#define JGATE 2048           // 4*H
#define EPSF  1e-8f
#define NCHUNK 16            // sim/stats chunks per (b,r)

// ------------------------- persistent device state -------------------------
__device__ float g_h[2][BB * HHD];               // ping-pong hidden state
__device__ float g_c[BB * HHD];
__device__ float g_M[BB * NND * WWD];            // 33.5 MB
__device__ float g_usage[BB * NND];
__device__ float g_rwsum[2][BB * NND];           // ping-pong sum_r(read_w)
__device__ float g_read_vec[BB * RRD * WWD];
__device__ float g_sim[BB * RRD * NND];          // raw cosine sims
__device__ float2 g_stats[BB * RRD * NCHUNK];    // per-chunk (max, sumexp)
__device__ float g_P[NCHUNK * BB * RRD * WWD];   // chunk partials for read_vec
__device__ float g_Kn[BB * RRD * WWD];           // normalized read keys
__device__ float g_wkey[2][BB * WWD];            // ping-pong write key
__device__ int   g_lu[2][BB];                    // ping-pong argmin(usage)

// ------------------------------- reset -------------------------------------
__global__ void k_reset() {
    long idx = (long)blockIdx.x * blockDim.x + threadIdx.x;
    if (idx < (long)BB * NND * WWD) g_M[idx] = 1e-6f;
    if (idx < BB * HHD) { g_h[0][idx] = 0.f; g_h[1][idx] = 0.f; g_c[idx] = 0.f; }
    if (idx < BB * NND) { g_usage[idx] = 0.f; g_rwsum[0][idx] = 0.f; g_rwsum[1][idx] = 0.f; }
    if (idx < BB * RRD * WWD) g_read_vec[idx] = 0.f;
    if (idx < BB * WWD) { g_wkey[0][idx] = 0.f; g_wkey[1][idx] = 0.f; }
    if (idx < BB) { g_lu[0][idx] = 0; g_lu[1][idx] = 0; }
}

__device__ __forceinline__ float sigm(float x) { return 1.f / (1.f + expf(-x)); }

// ==================== K1: gates GEMM + LSTM epilogue ========================
// grid 128 blocks x 256 threads. Block bid owns hh0 = bid*4: the 4 hidden
// units hh0..hh0+3 across ALL 4 gates (16 j values), all 64 batches, full K.
// Register double-buffering: tile t+1 loads overlap tile t compute.
__global__ void __launch_bounds__(256) k_gates(
    const float* __restrict__ xt,
    const float* __restrict__ Wih, const float* __restrict__ Whh,
    const float* __restrict__ bih, const float* __restrict__ bhh,
    int sel)
{
    __shared__ __align__(16) float4 xs4[BB * 16];   // 64 b x 64 k = 16 KB
    __shared__ __align__(16) float4 ws4[16 * 17];   // 16 j x 64 k padded
    __shared__ float sacc[16][BB];                  // acc staging, 4 KB

    const int tid = threadIdx.x;
    const int hq  = tid & 15;       // jj
    const int bq  = tid >> 4;       // 16 batch quads
    const int hh0 = blockIdx.x * 4;
    const float* __restrict__ hr = g_h[sel];

    const int xb   = tid >> 4;
    const int xk4  = tid & 15;
    const int wr_r = tid >> 4;
    const int jr   = hh0 + (wr_r & 3) + (wr_r >> 2) * 512;

    float acc[4] = {0.f, 0.f, 0.f, 0.f};

    float4 xreg[4];
    float4 wreg;

    {
        const int k0 = 0;
#pragma unroll
        for (int li = 0; li < 4; ++li) {
            int b = xb + 16 * li;
            int k = k0 + xk4 * 4;
            const float* src;
            if (k < INW)       src = xt + b * INW + k;
            else if (k < CTRL) src = g_read_vec + b * (RRD * WWD) + (k - INW);
            else               src = hr + b * HHD + (k - CTRL);
            xreg[li] = *reinterpret_cast<const float4*>(src);
        }
        int k = k0 + xk4 * 4;
        const float* src = (k < CTRL) ? (Wih + (size_t)jr * CTRL + k)
                                      : (Whh + (size_t)jr * HHD + (k - CTRL));
        wreg = *reinterpret_cast<const float4*>(src);
    }

    for (int tl = 0; tl < 14; ++tl) {
#pragma unroll
        for (int li = 0; li < 4; ++li)
            xs4[(xb + 16 * li) * 16 + xk4] = xreg[li];
        ws4[wr_r * 17 + xk4] = wreg;
        __syncthreads();

        if (tl + 1 < 14) {
            const int k0 = (tl + 1) * 64;
#pragma unroll
            for (int li = 0; li < 4; ++li) {
                int b = xb + 16 * li;
                int k = k0 + xk4 * 4;
                const float* src;
                if (k < INW)       src = xt + b * INW + k;
                else if (k < CTRL) src = g_read_vec + b * (RRD * WWD) + (k - INW);
                else               src = hr + b * HHD + (k - CTRL);
                xreg[li] = *reinterpret_cast<const float4*>(src);
            }
            int k = k0 + xk4 * 4;
            const float* src = (k < CTRL) ? (Wih + (size_t)jr * CTRL + k)
                                          : (Whh + (size_t)jr * HHD + (k - CTRL));
            wreg = *reinterpret_cast<const float4*>(src);
        }

#pragma unroll
        for (int kk = 0; kk < 16; ++kk) {
            float4 wv = ws4[hq * 17 + kk];
#pragma unroll
            for (int i = 0; i < 4; ++i) {
                float4 xv = xs4[(bq * 4 + i) * 16 + kk];
                acc[i] += xv.x * wv.x + xv.y * wv.y + xv.z * wv.z + xv.w * wv.w;
            }
        }
        __syncthreads();
    }

#pragma unroll
    for (int i = 0; i < 4; ++i) sacc[hq][bq * 4 + i] = acc[i];
    __syncthreads();

    {
        const int b  = tid & 63;
        const int dd = tid >> 6;
        const int hh = hh0 + dd;
        float gi = sacc[0 * 4 + dd][b] + bih[hh]           + bhh[hh];
        float gf = sacc[1 * 4 + dd][b] + bih[512 + hh]     + bhh[512 + hh];
        float gg = sacc[2 * 4 + dd][b] + bih[1024 + hh]    + bhh[1024 + hh];
        float go = sacc[3 * 4 + dd][b] + bih[1536 + hh]    + bhh[1536 + hh];
        float c  = g_c[b * HHD + hh];
        float cn = sigm(gf) * c + sigm(gi) * tanhf(gg);
        float hn = sigm(go) * tanhf(cn);
        g_c[b * HHD + hh] = cn;
        g_h[sel ^ 1][b * HHD + hh] = hn;
    }
}

// ========== K2: out+keys GEMM with fused finish epilogue + argmin ===========
// grid (8 j-groups, 32 batch-pairs) x 256 threads.
//   jg 0,1  -> out rows (bias bout)
//   jg 2..5 -> read key r=jg-2: add bkey, L2-normalize, write g_Kn
//   jg 6    -> write key: add bkey, write g_wkey[t&1]
//   jg 7    -> argmin(usage) for the 2 batches -> g_lu[t&1]
__global__ void __launch_bounds__(256) k_ok2(
    const float* __restrict__ Wout, const float* __restrict__ Wkey,
    const float* __restrict__ bout, const float* __restrict__ bkey,
    float* __restrict__ out, int t, int sel)
{
    __shared__ __align__(16) float4 hs[2][128];   // 2 batches x 512 floats
    __shared__ float ys[2][64];
    __shared__ float sinv[2];
    __shared__ float asv[256];
    __shared__ int   asi[256];

    const int tid  = threadIdx.x;
    const int wid  = tid >> 5, lane = tid & 31;
    const int jg   = blockIdx.x;
    const int b0   = blockIdx.y * 2;

    if (jg == 7) {
        const int half = tid >> 7;
        const int ht   = tid & 127;
        const int b    = b0 + half;
        float bv = 3.4e38f; int bi = 0;
        for (int i = ht; i < NND; i += 128) {
            float u = g_usage[b * NND + i];
            if (u < bv) { bv = u; bi = i; }
        }
        asv[tid] = bv; asi[tid] = bi;
        __syncthreads();
        for (int s = 64; s; s >>= 1) {
            if (ht < s) {
                float ov = asv[tid + s]; int oi = asi[tid + s];
                if (ov < asv[tid] || (ov == asv[tid] && oi < asi[tid])) {
                    asv[tid] = ov; asi[tid] = oi;
                }
            }
            __syncthreads();
        }
        if (ht == 0) g_lu[t & 1][b] = asi[tid];
        return;
    }

    const int j0 = jg * 64;
    const float* __restrict__ hn = g_h[sel ^ 1];

    {
        int bb = tid >> 7, idx = tid & 127;
        hs[bb][idx] = ((const float4*)(hn + (size_t)(b0 + bb) * HHD))[idx];
    }
    __syncthreads();

#pragma unroll 2
    for (int jj = 0; jj < 8; ++jj) {
        int j = j0 + wid * 8 + jj;
        const float* wrow = (j < OUTW) ? (Wout + (size_t)j * HHD)
                                       : (Wkey + (size_t)(j - OUTW) * HHD);
        const float4* w4 = (const float4*)wrow;
        float s0 = 0.f, s1 = 0.f;
#pragma unroll
        for (int it = 0; it < 4; ++it) {
            float4 w = w4[lane + 32 * it];
            float4 h0 = hs[0][lane + 32 * it];
            float4 h1 = hs[1][lane + 32 * it];
            s0 += w.x * h0.x + w.y * h0.y + w.z * h0.z + w.w * h0.w;
            s1 += w.x * h1.x + w.y * h1.y + w.z * h1.z + w.w * h1.w;
        }
#pragma unroll
        for (int o = 16; o; o >>= 1) {
            s0 += __shfl_xor_sync(0xffffffffu, s0, o);
            s1 += __shfl_xor_sync(0xffffffffu, s1, o);
        }
        if (lane == 0) { ys[0][wid * 8 + jj] = s0; ys[1][wid * 8 + jj] = s1; }
    }
    __syncthreads();

    if (jg < 2) {
        if (tid < 128) {
            int bb = tid >> 6, jj = tid & 63;
            out[(size_t)t * BB * OUTW + (size_t)(b0 + bb) * OUTW + j0 + jj] =
                ys[bb][jj] + bout[j0 + jj];
        }
    } else if (jg == 6) {
        if (tid < 128) {
            int bb = tid >> 6, jj = tid & 63;
            g_wkey[t & 1][(b0 + bb) * WWD + jj] = ys[bb][jj] + bkey[4 * 64 + jj];
        }
    } else {
        const int kb = (jg - 2) * 64;
        if (tid < 128) {
            int bb = tid >> 6, jj = tid & 63;
            ys[bb][jj] += bkey[kb + jj];
        }
        __syncthreads();
        if (wid < 2) {
            float v0 = ys[wid][lane];
            float v1 = ys[wid][lane + 32];
            float ss = v0 * v0 + v1 * v1;
#pragma unroll
            for (int o = 16; o; o >>= 1) ss += __shfl_xor_sync(0xffffffffu, ss, o);
            if (lane == 0) sinv[wid] = 1.f / (sqrtf(ss) + EPSF);
        }
        __syncthreads();
        if (tid < 128) {
            int bb = tid >> 6, jj = tid & 63;
            g_Kn[(b0 + bb) * (RRD * WWD) + kb + jj] = ys[bb][jj] * sinv[bb];
        }
    }
}

// ===== K3: lazy M-update + sim + stats + chunk partials (one M stream) ======
// grid (16, BB) x 256 threads, 3 blocks/SM target. Block (nb, b):
//  1. applies the PREVIOUS step's memory write to its 128 M rows while
//     staging them (RMW riding the stream sim needs anyway),
//  2. cosine sims: each thread reduces HALF a row (32 w), halves combined
//     via a smem exchange,
//  3. emits chunk (max, sumexp) stats,
//  4. emits chunk partials P[r][w] = sum_n exp(sim - m_c) * M[n][w]
//     (one (r,w) pair per thread -> 128 FMA).
__global__ void __launch_bounds__(256, 3) k_simup(const float* __restrict__ alpha,
                                                  int t) {
    __shared__ float tA[128 * 33];                   // w 0..31, pitch 33
    __shared__ float tB[128 * 33];                   // w 32..63
    __shared__ __align__(16) float s_kn[RRD * WWD];  // 1 KB
    __shared__ __align__(16) float s_wk[WWD];
    __shared__ float s_ww[128];
    __shared__ float s_part[5][256];                 // 5 KB half-row exchange
    __shared__ float s_sv[4][128];
    __shared__ float s_e[4][128];
    __shared__ float s_mc[4];

    const int b    = blockIdx.y;
    const int nb   = blockIdx.x;
    const int tid  = threadIdx.x;    // 256
    const int wid  = tid >> 5, lane = tid & 31;
    const int n0   = nb * 128;
    const int prev = (t & 1) ^ 1;
    const bool apply = (t > 0);
    const float sa = 1.f / (1.f + expf(-alpha[0]));

    s_kn[tid] = g_Kn[b * RRD * WWD + tid];
    if (tid < WWD) s_wk[tid] = g_wkey[prev][b * WWD + tid];
    const int lu = g_lu[prev][b];
    if (tid >= 128) {
        int rr = tid - 128;
        float rs = g_rwsum[t & 1][b * NND + n0 + rr];
        s_ww[rr] = sa * rs + ((n0 + rr) == lu ? (1.f - sa) : 0.f);
    }
    __syncthreads();

    float* Mrow = g_M + ((size_t)b * NND + n0) * WWD;

    // stage whole tile (128 rows x 16 float4), applying pending update
#pragma unroll
    for (int i = 0; i < 8; ++i) {
        int fid = tid + 256 * i;
        int row = fid >> 4, c4 = fid & 15;
        float4* gp = (float4*)(Mrow + (size_t)row * WWD) + c4;
        float4 v = *gp;
        if (apply) {
            float ww = s_ww[row];
            const float4 wk4 = *(const float4*)(s_wk + c4 * 4);
            bool islu = (n0 + row) == lu;
            v.x = (islu ? 0.f : v.x) + ww * wk4.x;
            v.y = (islu ? 0.f : v.y) + ww * wk4.y;
            v.z = (islu ? 0.f : v.z) + ww * wk4.z;
            v.w = (islu ? 0.f : v.w) + ww * wk4.w;
            *gp = v;
        }
        float* dst = ((c4 < 8) ? tA : tB) + row * 33 + (c4 & 7) * 4;
        dst[0] = v.x; dst[1] = v.y; dst[2] = v.z; dst[3] = v.w;
    }
    __syncthreads();

    // half-row reduction: thread owns (row = tid&127, half = tid>>7)
    {
        const int row = tid & 127, half = tid >> 7;
        const float* tr = (half ? tB : tA) + row * 33;
        const float4* kk0 = (const float4*)(s_kn + 0 * 64 + half * 32);
        const float4* kk1 = (const float4*)(s_kn + 1 * 64 + half * 32);
        const float4* kk2 = (const float4*)(s_kn + 2 * 64 + half * 32);
        const float4* kk3 = (const float4*)(s_kn + 3 * 64 + half * 32);
        float ss = 0.f, d0 = 0.f, d1 = 0.f, d2 = 0.f, d3 = 0.f;
#pragma unroll
        for (int w4 = 0; w4 < 8; ++w4) {
            float m0 = tr[w4 * 4 + 0];
            float m1 = tr[w4 * 4 + 1];
            float m2 = tr[w4 * 4 + 2];
            float m3 = tr[w4 * 4 + 3];
            float4 a = kk0[w4], bb = kk1[w4], c = kk2[w4], d = kk3[w4];
            ss += m0 * m0 + m1 * m1 + m2 * m2 + m3 * m3;
            d0 += m0 * a.x + m1 * a.y + m2 * a.z + m3 * a.w;
            d1 += m0 * bb.x + m1 * bb.y + m2 * bb.z + m3 * bb.w;
            d2 += m0 * c.x + m1 * c.y + m2 * c.z + m3 * c.w;
            d3 += m0 * d.x + m1 * d.y + m2 * d.z + m3 * d.w;
        }
        s_part[0][tid] = ss;
        s_part[1][tid] = d0;
        s_part[2][tid] = d1;
        s_part[3][tid] = d2;
        s_part[4][tid] = d3;
    }
    __syncthreads();

    if (tid < 128) {
        float ss = s_part[0][tid] + s_part[0][tid + 128];
        float d0 = s_part[1][tid] + s_part[1][tid + 128];
        float d1 = s_part[2][tid] + s_part[2][tid + 128];
        float d2 = s_part[3][tid] + s_part[3][tid + 128];
        float d3 = s_part[4][tid] + s_part[4][tid + 128];
        float inv = 1.f / (sqrtf(ss) + EPSF);
        float s0 = d0 * inv, s1 = d1 * inv, s2 = d2 * inv, s3 = d3 * inv;
        const int n = n0 + tid;
        g_sim[(size_t)(b * RRD + 0) * NND + n] = s0;
        g_sim[(size_t)(b * RRD + 1) * NND + n] = s1;
        g_sim[(size_t)(b * RRD + 2) * NND + n] = s2;
        g_sim[(size_t)(b * RRD + 3) * NND + n] = s3;
        s_sv[0][tid] = s0; s_sv[1][tid] = s1; s_sv[2][tid] = s2; s_sv[3][tid] = s3;
    }
    __syncthreads();

    // warps 0-3: chunk stats for r = wid
    if (wid < 4) {
        float v0 = s_sv[wid][lane];
        float v1 = s_sv[wid][lane + 32];
        float v2 = s_sv[wid][lane + 64];
        float v3 = s_sv[wid][lane + 96];
        float m = fmaxf(fmaxf(v0, v1), fmaxf(v2, v3));
#pragma unroll
        for (int o = 16; o; o >>= 1) m = fmaxf(m, __shfl_xor_sync(0xffffffffu, m, o));
        float S = expf(v0 - m) + expf(v1 - m) + expf(v2 - m) + expf(v3 - m);
#pragma unroll
        for (int o = 16; o; o >>= 1) S += __shfl_xor_sync(0xffffffffu, S, o);
        if (lane == 0) {
            g_stats[(b * RRD + wid) * NCHUNK + nb] = make_float2(m, S);
            s_mc[wid] = m;
        }
    }
    __syncthreads();

    // chunk-normalized exps (512 values / 256 threads)
#pragma unroll
    for (int k2 = 0; k2 < 2; ++k2) {
        int idx = tid + 256 * k2;
        int r = idx >> 7, nn = idx & 127;
        s_e[r][nn] = expf(s_sv[r][nn] - s_mc[r]);
    }
    __syncthreads();

    // chunk partials: thread owns (r = tid>>6, w = tid&63), 128 FMA
    {
        const int w = tid & 63;
        const int r = tid >> 6;
        const float* tcol = ((w < 32) ? tA : tB) + (w & 31);
        const float* er = s_e[r];
        float p = 0.f;
#pragma unroll 8
        for (int nn = 0; nn < 128; ++nn)
            p += er[nn] * tcol[nn * 33];
        g_P[((size_t)(nb * BB + b) * RRD + r) * WWD + w] = p;
    }
}

// ===== K4: finalize — stats combine, rwsum + usage, read_vec (no M pass) ====
// grid (16, BB) x 256 threads. cx==0 block additionally assembles read_vec.
__global__ void __launch_bounds__(256) k_final(const float* __restrict__ alpha,
                                               const float* __restrict__ gamma,
                                               int t) {
    __shared__ float2 s_st[4 * NCHUNK];
    __shared__ float s_m[4], s_is[4];
    __shared__ float srw[4][128];

    const int b   = blockIdx.y;
    const int cx  = blockIdx.x;
    const int tid = threadIdx.x;
    const int cur = t & 1, prev = cur ^ 1;
    const float sa = 1.f / (1.f + expf(-alpha[0]));
    const float gm = gamma[0];
    const int lu = g_lu[cur][b];

    if (tid < 64) s_st[tid] = g_stats[(b * RRD + (tid >> 4)) * NCHUNK + (tid & 15)];
    __syncthreads();
    if (tid < 4) {
        float m = -3.4e38f;
#pragma unroll
        for (int i = 0; i < NCHUNK; ++i) m = fmaxf(m, s_st[tid * NCHUNK + i].x);
        float S = 0.f;
#pragma unroll
        for (int i = 0; i < NCHUNK; ++i) {
            float2 p = s_st[tid * NCHUNK + i];
            S += p.y * expf(p.x - m);
        }
        s_m[tid] = m; s_is[tid] = 1.f / S;
    }
    __syncthreads();

    const int n0 = cx * 128;
#pragma unroll
    for (int k2 = 0; k2 < 2; ++k2) {
        int idx = tid + 256 * k2;
        int r = idx >> 7, nl = idx & 127;
        float sv = g_sim[(size_t)(b * RRD + r) * NND + n0 + nl];
        srw[r][nl] = expf(sv - s_m[r]) * s_is[r];
    }
    __syncthreads();

    if (tid < 128) {
        int nn = n0 + tid;
        float rsum = srw[0][tid] + srw[1][tid] + srw[2][tid] + srw[3][tid];
        g_rwsum[cur][b * NND + nn] = rsum;
        float rprev = g_rwsum[prev][b * NND + nn];
        float wwt = sa * rprev + ((nn == lu) ? (1.f - sa) : 0.f);
        g_usage[b * NND + nn] = gm * g_usage[b * NND + nn] + rsum + wwt;
    }

    // read_vec assembly: only cx==0 block (direct write, no atomics)
    if (cx == 0) {
        const int r = tid >> 6, w = tid & 63;
        float m = s_m[r], is = s_is[r];
        float rv = 0.f;
#pragma unroll
        for (int c = 0; c < NCHUNK; ++c) {
            float2 st = s_st[r * NCHUNK + c];
            rv += expf(st.x - m) * g_P[((size_t)(c * BB + b) * RRD + r) * WWD + w];
        }
        g_read_vec[b * RRD * WWD + tid] = rv * is;
    }
}

// ------------------------------- launcher ------------------------------------
extern "C" void kernel_launch(void* const* d_in, const int* in_sizes, int n_in,
                              void* d_out, int out_size) {
    const float* x_seq = (const float*)d_in[0];
    const float* Wih   = (const float*)d_in[1];
    const float* Whh   = (const float*)d_in[2];
    const float* bih   = (const float*)d_in[3];
    const float* bhh   = (const float*)d_in[4];
    const float* Wout  = (const float*)d_in[5];
    const float* bout  = (const float*)d_in[6];
    const float* Wkey  = (const float*)d_in[7];
    const float* bkey  = (const float*)d_in[8];
    const float* alpha = (const float*)d_in[9];
    const float* gamma = (const float*)d_in[10];
    float* out = (float*)d_out;

    k_reset<<<32768, 256>>>();

    for (int t = 0; t < TT; ++t) {
        const int sel = t & 1;
        k_gates<<<JGATE / 16, 256>>>(x_seq + (size_t)t * BB * INW,
                                     Wih, Whh, bih, bhh, sel);
        k_ok2<<<dim3(8, 32), 256>>>(Wout, Wkey, bout, bkey, out, t, sel);
        k_simup<<<dim3(NCHUNK, BB), 256>>>(alpha, t);
        k_final<<<dim3(16, BB), 256>>>(alpha, gamma, t);
    }
}

// round 15
// speedup vs baseline: 1.0633x; 1.0633x over previous
#include <cuda_runtime.h>
#include <math.h>
#include <stdint.h>

// Problem constants
#define BB    64
#define TT    128
#define INW   128
#define HHD   512
#define NND   2048
#define WWD   64
#define OUTW  128
#define RRD   4
#define CTRL  384            // IN + R*W
#define JGATE 2048           // 4*H
#define EPSF  1e-8f
#define NCHUNK 16            // sim/stats chunks per (b,r)

// PDL: wait for the previous kernel's memory to be visible.
__device__ __forceinline__ void pdl_wait() {
    asm volatile("griddepcontrol.wait;" ::: "memory");
}

// ------------------------- persistent device state -------------------------
__device__ float g_h[2][BB * HHD];               // ping-pong hidden state
__device__ float g_c[BB * HHD];
__device__ float g_M[BB * NND * WWD];            // 33.5 MB
__device__ float g_usage[BB * NND];
__device__ float g_rwsum[2][BB * NND];           // ping-pong sum_r(read_w)
__device__ float g_read_vec[BB * RRD * WWD];
__device__ float g_sim[BB * RRD * NND];          // raw cosine sims
__device__ float2 g_stats[BB * RRD * NCHUNK];    // per-chunk (max, sumexp)
__device__ float g_P[NCHUNK * BB * RRD * WWD];   // chunk partials for read_vec
__device__ float g_Kn[BB * RRD * WWD];           // normalized read keys
__device__ float g_wkey[2][BB * WWD];            // ping-pong write key
__device__ int   g_lu[2][BB];                    // ping-pong argmin(usage)

// ------------------------------- reset -------------------------------------
__global__ void k_reset() {
    long idx = (long)blockIdx.x * blockDim.x + threadIdx.x;
    if (idx < (long)BB * NND * WWD) g_M[idx] = 1e-6f;
    if (idx < BB * HHD) { g_h[0][idx] = 0.f; g_h[1][idx] = 0.f; g_c[idx] = 0.f; }
    if (idx < BB * NND) { g_usage[idx] = 0.f; g_rwsum[0][idx] = 0.f; g_rwsum[1][idx] = 0.f; }
    if (idx < BB * RRD * WWD) g_read_vec[idx] = 0.f;
    if (idx < BB * WWD) { g_wkey[0][idx] = 0.f; g_wkey[1][idx] = 0.f; }
    if (idx < BB) { g_lu[0][idx] = 0; g_lu[1][idx] = 0; }
}

__device__ __forceinline__ float sigm(float x) { return 1.f / (1.f + expf(-x)); }

// ==================== K1: gates GEMM + LSTM epilogue ========================
// grid 128 blocks x 256 threads. Block bid owns hh0 = bid*4: the 4 hidden
// units hh0..hh0+3 across ALL 4 gates (16 j values), all 64 batches, full K.
// Register double-buffering; W prefetch overlaps predecessor tail via PDL.
__global__ void __launch_bounds__(256) k_gates(
    const float* __restrict__ xt,
    const float* __restrict__ Wih, const float* __restrict__ Whh,
    const float* __restrict__ bih, const float* __restrict__ bhh,
    int sel)
{
    __shared__ __align__(16) float4 xs4[BB * 16];   // 64 b x 64 k = 16 KB
    __shared__ __align__(16) float4 ws4[16 * 17];   // 16 j x 64 k padded
    __shared__ float sacc[16][BB];                  // acc staging, 4 KB

    const int tid = threadIdx.x;
    const int hq  = tid & 15;       // jj
    const int bq  = tid >> 4;       // 16 batch quads
    const int hh0 = blockIdx.x * 4;
    const float* __restrict__ hr = g_h[sel];

    const int xb   = tid >> 4;
    const int xk4  = tid & 15;
    const int wr_r = tid >> 4;
    const int jr   = hh0 + (wr_r & 3) + (wr_r >> 2) * 512;

    float acc[4] = {0.f, 0.f, 0.f, 0.f};

    float4 xreg[4];
    float4 wreg;

    // W prefetch: weights are pure inputs, independent of prior kernels.
    {
        int k = xk4 * 4;
        const float* src = (k < CTRL) ? (Wih + (size_t)jr * CTRL + k)
                                      : (Whh + (size_t)jr * HHD + (k - CTRL));
        wreg = *reinterpret_cast<const float4*>(src);
    }

    // Wait for predecessor (k_final of prev step) before touching read_vec/h.
    pdl_wait();

    {
        const int k0 = 0;
#pragma unroll
        for (int li = 0; li < 4; ++li) {
            int b = xb + 16 * li;
            int k = k0 + xk4 * 4;
            const float* src;
            if (k < INW)       src = xt + b * INW + k;
            else if (k < CTRL) src = g_read_vec + b * (RRD * WWD) + (k - INW);
            else               src = hr + b * HHD + (k - CTRL);
            xreg[li] = *reinterpret_cast<const float4*>(src);
        }
    }

    for (int tl = 0; tl < 14; ++tl) {
#pragma unroll
        for (int li = 0; li < 4; ++li)
            xs4[(xb + 16 * li) * 16 + xk4] = xreg[li];
        ws4[wr_r * 17 + xk4] = wreg;
        __syncthreads();

        if (tl + 1 < 14) {
            const int k0 = (tl + 1) * 64;
#pragma unroll
            for (int li = 0; li < 4; ++li) {
                int b = xb + 16 * li;
                int k = k0 + xk4 * 4;
                const float* src;
                if (k < INW)       src = xt + b * INW + k;
                else if (k < CTRL) src = g_read_vec + b * (RRD * WWD) + (k - INW);
                else               src = hr + b * HHD + (k - CTRL);
                xreg[li] = *reinterpret_cast<const float4*>(src);
            }
            int k = k0 + xk4 * 4;
            const float* src = (k < CTRL) ? (Wih + (size_t)jr * CTRL + k)
                                          : (Whh + (size_t)jr * HHD + (k - CTRL));
            wreg = *reinterpret_cast<const float4*>(src);
        }

#pragma unroll
        for (int kk = 0; kk < 16; ++kk) {
            float4 wv = ws4[hq * 17 + kk];
#pragma unroll
            for (int i = 0; i < 4; ++i) {
                float4 xv = xs4[(bq * 4 + i) * 16 + kk];
                acc[i] += xv.x * wv.x + xv.y * wv.y + xv.z * wv.z + xv.w * wv.w;
            }
        }
        __syncthreads();
    }

#pragma unroll
    for (int i = 0; i < 4; ++i) sacc[hq][bq * 4 + i] = acc[i];
    __syncthreads();

    {
        const int b  = tid & 63;
        const int dd = tid >> 6;
        const int hh = hh0 + dd;
        float gi = sacc[0 * 4 + dd][b] + bih[hh]           + bhh[hh];
        float gf = sacc[1 * 4 + dd][b] + bih[512 + hh]     + bhh[512 + hh];
        float gg = sacc[2 * 4 + dd][b] + bih[1024 + hh]    + bhh[1024 + hh];
        float go = sacc[3 * 4 + dd][b] + bih[1536 + hh]    + bhh[1536 + hh];
        float c  = g_c[b * HHD + hh];
        float cn = sigm(gf) * c + sigm(gi) * tanhf(gg);
        float hn = sigm(go) * tanhf(cn);
        g_c[b * HHD + hh] = cn;
        g_h[sel ^ 1][b * HHD + hh] = hn;
    }
}

// ========== K2: out+keys GEMM with fused finish epilogue + argmin ===========
// grid (8 j-groups, 32 batch-pairs) x 256 threads.
//   jg 0,1  -> out rows (bias bout)
//   jg 2..5 -> read key r=jg-2: add bkey, L2-normalize, write g_Kn
//   jg 6    -> write key: add bkey, write g_wkey[t&1]
//   jg 7    -> argmin(usage) for the 2 batches -> g_lu[t&1]
__global__ void __launch_bounds__(256) k_ok2(
    const float* __restrict__ Wout, const float* __restrict__ Wkey,
    const float* __restrict__ bout, const float* __restrict__ bkey,
    float* __restrict__ out, int t, int sel)
{
    __shared__ __align__(16) float4 hs[2][128];   // 2 batches x 512 floats
    __shared__ float ys[2][64];
    __shared__ float sinv[2];
    __shared__ float asv[256];
    __shared__ int   asi[256];

    const int tid  = threadIdx.x;
    const int wid  = tid >> 5, lane = tid & 31;
    const int jg   = blockIdx.x;
    const int b0   = blockIdx.y * 2;

    pdl_wait();

    if (jg == 7) {
        const int half = tid >> 7;
        const int ht   = tid & 127;
        const int b    = b0 + half;
        float bv = 3.4e38f; int bi = 0;
        for (int i = ht; i < NND; i += 128) {
            float u = g_usage[b * NND + i];
            if (u < bv) { bv = u; bi = i; }
        }
        asv[tid] = bv; asi[tid] = bi;
        __syncthreads();
        for (int s = 64; s; s >>= 1) {
            if (ht < s) {
                float ov = asv[tid + s]; int oi = asi[tid + s];
                if (ov < asv[tid] || (ov == asv[tid] && oi < asi[tid])) {
                    asv[tid] = ov; asi[tid] = oi;
                }
            }
            __syncthreads();
        }
        if (ht == 0) g_lu[t & 1][b] = asi[tid];
        return;
    }

    const int j0 = jg * 64;
    const float* __restrict__ hn = g_h[sel ^ 1];

    {
        int bb = tid >> 7, idx = tid & 127;
        hs[bb][idx] = ((const float4*)(hn + (size_t)(b0 + bb) * HHD))[idx];
    }
    __syncthreads();

#pragma unroll 2
    for (int jj = 0; jj < 8; ++jj) {
        int j = j0 + wid * 8 + jj;
        const float* wrow = (j < OUTW) ? (Wout + (size_t)j * HHD)
                                       : (Wkey + (size_t)(j - OUTW) * HHD);
        const float4* w4 = (const float4*)wrow;
        float s0 = 0.f, s1 = 0.f;
#pragma unroll
        for (int it = 0; it < 4; ++it) {
            float4 w = w4[lane + 32 * it];
            float4 h0 = hs[0][lane + 32 * it];
            float4 h1 = hs[1][lane + 32 * it];
            s0 += w.x * h0.x + w.y * h0.y + w.z * h0.z + w.w * h0.w;
            s1 += w.x * h1.x + w.y * h1.y + w.z * h1.z + w.w * h1.w;
        }
#pragma unroll
        for (int o = 16; o; o >>= 1) {
            s0 += __shfl_xor_sync(0xffffffffu, s0, o);
            s1 += __shfl_xor_sync(0xffffffffu, s1, o);
        }
        if (lane == 0) { ys[0][wid * 8 + jj] = s0; ys[1][wid * 8 + jj] = s1; }
    }
    __syncthreads();

    if (jg < 2) {
        if (tid < 128) {
            int bb = tid >> 6, jj = tid & 63;
            out[(size_t)t * BB * OUTW + (size_t)(b0 + bb) * OUTW + j0 + jj] =
                ys[bb][jj] + bout[j0 + jj];
        }
    } else if (jg == 6) {
        if (tid < 128) {
            int bb = tid >> 6, jj = tid & 63;
            g_wkey[t & 1][(b0 + bb) * WWD + jj] = ys[bb][jj] + bkey[4 * 64 + jj];
        }
    } else {
        const int kb = (jg - 2) * 64;
        if (tid < 128) {
            int bb = tid >> 6, jj = tid & 63;
            ys[bb][jj] += bkey[kb + jj];
        }
        __syncthreads();
        if (wid < 2) {
            float v0 = ys[wid][lane];
            float v1 = ys[wid][lane + 32];
            float ss = v0 * v0 + v1 * v1;
#pragma unroll
            for (int o = 16; o; o >>= 1) ss += __shfl_xor_sync(0xffffffffu, ss, o);
            if (lane == 0) sinv[wid] = 1.f / (sqrtf(ss) + EPSF);
        }
        __syncthreads();
        if (tid < 128) {
            int bb = tid >> 6, jj = tid & 63;
            g_Kn[(b0 + bb) * (RRD * WWD) + kb + jj] = ys[bb][jj] * sinv[bb];
        }
    }
}

// ===== K3: lazy M-update + sim + stats + chunk partials (one M stream) ======
// grid (16, BB) x 128 threads. Block (nb, b):
//  1. applies the PREVIOUS step's memory write to its 128 M rows while
//     staging them (read-modify-write, riding the stream sim needs anyway),
//  2. computes cosine sims (per-thread rows, zero shuffles),
//  3. emits chunk (max, sumexp) stats,
//  4. emits chunk partials P[r][w] = sum_n exp(sim - m_c) * M[n][w].
__global__ void __launch_bounds__(128) k_simup(const float* __restrict__ alpha,
                                               int t) {
    __shared__ float tA[128 * 33];                   // w 0..31, pitch 33
    __shared__ float tB[128 * 33];                   // w 32..63
    __shared__ __align__(16) float s_kn[RRD * WWD];  // 1 KB
    __shared__ __align__(16) float s_wk[WWD];
    __shared__ float s_ww[128];
    __shared__ float s_sv[4][128];
    __shared__ float s_e[4][128];
    __shared__ float s_mc[4];

    const int b    = blockIdx.y;
    const int nb   = blockIdx.x;
    const int tid  = threadIdx.x;    // 128
    const int wid  = tid >> 5, lane = tid & 31;
    const int n0   = nb * 128;
    const int prev = (t & 1) ^ 1;
    const bool apply = (t > 0);
    const float sa = 1.f / (1.f + expf(-alpha[0]));

    pdl_wait();

    s_kn[tid]       = g_Kn[b * RRD * WWD + tid];
    s_kn[tid + 128] = g_Kn[b * RRD * WWD + tid + 128];
    if (tid < WWD) s_wk[tid] = g_wkey[prev][b * WWD + tid];
    const int lu = g_lu[prev][b];
    {
        // ww for pending update: uses rwsum from step t-2 (buffer t&1)
        float rs = g_rwsum[t & 1][b * NND + n0 + tid];
        s_ww[tid] = sa * rs + ((n0 + tid) == lu ? (1.f - sa) : 0.f);
    }
    __syncthreads();

    float* Mrow = g_M + ((size_t)b * NND + n0) * WWD;

    // stage both halves, applying the pending update in-stream
#pragma unroll
    for (int ph = 0; ph < 2; ++ph) {
        float* tile = ph ? tB : tA;
#pragma unroll
        for (int i = 0; i < 8; ++i) {
            int fid = tid + 128 * i;
            int row = fid >> 3, c4 = fid & 7;
            float4* gp = (float4*)(Mrow + (size_t)row * WWD) + ph * 8 + c4;
            float4 v = *gp;
            if (apply) {
                float ww = s_ww[row];
                const float4 wk4 = *(const float4*)(s_wk + ph * 32 + c4 * 4);
                bool islu = (n0 + row) == lu;
                v.x = (islu ? 0.f : v.x) + ww * wk4.x;
                v.y = (islu ? 0.f : v.y) + ww * wk4.y;
                v.z = (islu ? 0.f : v.z) + ww * wk4.z;
                v.w = (islu ? 0.f : v.w) + ww * wk4.w;
                *gp = v;
            }
            float* dst = tile + row * 33 + c4 * 4;
            dst[0] = v.x; dst[1] = v.y; dst[2] = v.z; dst[3] = v.w;
        }
    }
    __syncthreads();

    // per-thread row reduction (row = tid)
    float ss = 0.f, d0 = 0.f, d1 = 0.f, d2 = 0.f, d3 = 0.f;
#pragma unroll
    for (int ph = 0; ph < 2; ++ph) {
        const float* tr = (ph ? tB : tA) + tid * 33;
        const float4* kk0 = (const float4*)(s_kn + 0 * 64 + ph * 32);
        const float4* kk1 = (const float4*)(s_kn + 1 * 64 + ph * 32);
        const float4* kk2 = (const float4*)(s_kn + 2 * 64 + ph * 32);
        const float4* kk3 = (const float4*)(s_kn + 3 * 64 + ph * 32);
#pragma unroll
        for (int w4 = 0; w4 < 8; ++w4) {
            float m0 = tr[w4 * 4 + 0];
            float m1 = tr[w4 * 4 + 1];
            float m2 = tr[w4 * 4 + 2];
            float m3 = tr[w4 * 4 + 3];
            float4 a = kk0[w4], bb = kk1[w4], c = kk2[w4], d = kk3[w4];
            ss += m0 * m0 + m1 * m1 + m2 * m2 + m3 * m3;
            d0 += m0 * a.x + m1 * a.y + m2 * a.z + m3 * a.w;
            d1 += m0 * bb.x + m1 * bb.y + m2 * bb.z + m3 * bb.w;
            d2 += m0 * c.x + m1 * c.y + m2 * c.z + m3 * c.w;
            d3 += m0 * d.x + m1 * d.y + m2 * d.z + m3 * d.w;
        }
    }

    float inv = 1.f / (sqrtf(ss) + EPSF);
    float s0 = d0 * inv, s1 = d1 * inv, s2 = d2 * inv, s3 = d3 * inv;
    const int n = n0 + tid;
    g_sim[(size_t)(b * RRD + 0) * NND + n] = s0;
    g_sim[(size_t)(b * RRD + 1) * NND + n] = s1;
    g_sim[(size_t)(b * RRD + 2) * NND + n] = s2;
    g_sim[(size_t)(b * RRD + 3) * NND + n] = s3;
    s_sv[0][tid] = s0; s_sv[1][tid] = s1; s_sv[2][tid] = s2; s_sv[3][tid] = s3;
    __syncthreads();

    // warp wid: chunk stats for r = wid
    {
        float v0 = s_sv[wid][lane];
        float v1 = s_sv[wid][lane + 32];
        float v2 = s_sv[wid][lane + 64];
        float v3 = s_sv[wid][lane + 96];
        float m = fmaxf(fmaxf(v0, v1), fmaxf(v2, v3));
#pragma unroll
        for (int o = 16; o; o >>= 1) m = fmaxf(m, __shfl_xor_sync(0xffffffffu, m, o));
        float S = expf(v0 - m) + expf(v1 - m) + expf(v2 - m) + expf(v3 - m);
#pragma unroll
        for (int o = 16; o; o >>= 1) S += __shfl_xor_sync(0xffffffffu, S, o);
        if (lane == 0) {
            g_stats[(b * RRD + wid) * NCHUNK + nb] = make_float2(m, S);
            s_mc[wid] = m;
        }
    }
    __syncthreads();

    // chunk-normalized exps
#pragma unroll
    for (int r = 0; r < 4; ++r)
        s_e[r][tid] = expf(s_sv[r][tid] - s_mc[r]);
    __syncthreads();

    // chunk partials P[r][w] = sum_n e[r][n] * M[n][w]
    {
        const int w  = tid & 63;
        const int rp = tid >> 6;   // 0 or 1; handles r = rp and rp+2
        const float* tcol = ((w < 32) ? tA : tB) + (w & 31);
        float p0 = 0.f, p1 = 0.f;
#pragma unroll 8
        for (int nn = 0; nn < 128; ++nn) {
            float tv = tcol[nn * 33];
            p0 += s_e[rp][nn]     * tv;
            p1 += s_e[rp + 2][nn] * tv;
        }
        g_P[((size_t)(nb * BB + b) * RRD + rp)     * WWD + w] = p0;
        g_P[((size_t)(nb * BB + b) * RRD + rp + 2) * WWD + w] = p1;
    }
}

// ===== K4: finalize — stats combine, rwsum + usage, read_vec (no M pass) ====
// grid (16, BB) x 256 threads. cx==0 block additionally assembles read_vec.
__global__ void __launch_bounds__(256) k_final(const float* __restrict__ alpha,
                                               const float* __restrict__ gamma,
                                               int t) {
    __shared__ float2 s_st[4 * NCHUNK];
    __shared__ float s_m[4], s_is[4];
    __shared__ float srw[4][128];

    const int b   = blockIdx.y;
    const int cx  = blockIdx.x;
    const int tid = threadIdx.x;
    const int cur = t & 1, prev = cur ^ 1;
    const float sa = 1.f / (1.f + expf(-alpha[0]));
    const float gm = gamma[0];

    pdl_wait();

    const int lu = g_lu[cur][b];

    if (tid < 64) s_st[tid] = g_stats[(b * RRD + (tid >> 4)) * NCHUNK + (tid & 15)];
    __syncthreads();
    if (tid < 4) {
        float m = -3.4e38f;
#pragma unroll
        for (int i = 0; i < NCHUNK; ++i) m = fmaxf(m, s_st[tid * NCHUNK + i].x);
        float S = 0.f;
#pragma unroll
        for (int i = 0; i < NCHUNK; ++i) {
            float2 p = s_st[tid * NCHUNK + i];
            S += p.y * expf(p.x - m);
        }
        s_m[tid] = m; s_is[tid] = 1.f / S;
    }
    __syncthreads();

    const int n0 = cx * 128;
#pragma unroll
    for (int k2 = 0; k2 < 2; ++k2) {
        int idx = tid + 256 * k2;
        int r = idx >> 7, nl = idx & 127;
        float sv = g_sim[(size_t)(b * RRD + r) * NND + n0 + nl];
        srw[r][nl] = expf(sv - s_m[r]) * s_is[r];
    }
    __syncthreads();

    if (tid < 128) {
        int nn = n0 + tid;
        float rsum = srw[0][tid] + srw[1][tid] + srw[2][tid] + srw[3][tid];
        g_rwsum[cur][b * NND + nn] = rsum;
        float rprev = g_rwsum[prev][b * NND + nn];
        float wwt = sa * rprev + ((nn == lu) ? (1.f - sa) : 0.f);
        g_usage[b * NND + nn] = gm * g_usage[b * NND + nn] + rsum + wwt;
    }

    // read_vec assembly: only cx==0 block (direct write, no atomics)
    if (cx == 0) {
        const int r = tid >> 6, w = tid & 63;
        float m = s_m[r], is = s_is[r];
        float rv = 0.f;
#pragma unroll
        for (int c = 0; c < NCHUNK; ++c) {
            float2 st = s_st[r * NCHUNK + c];
            rv += expf(st.x - m) * g_P[((size_t)(c * BB + b) * RRD + r) * WWD + w];
        }
        g_read_vec[b * RRD * WWD + tid] = rv * is;
    }
}

// ------------------------------- launcher ------------------------------------
static inline cudaLaunchConfig_t pdl_cfg(dim3 grid, dim3 block,
                                         cudaLaunchAttribute* attr) {
    cudaLaunchConfig_t cfg = {};
    cfg.gridDim = grid;
    cfg.blockDim = block;
    cfg.dynamicSmemBytes = 0;
    cfg.stream = 0;
    attr[0].id = cudaLaunchAttributeProgrammaticStreamSerialization;
    attr[0].val.programmaticStreamSerializationAllowed = 1;
    cfg.attrs = attr;
    cfg.numAttrs = 1;
    return cfg;
}

extern "C" void kernel_launch(void* const* d_in, const int* in_sizes, int n_in,
                              void* d_out, int out_size) {
    const float* x_seq = (const float*)d_in[0];
    const float* Wih   = (const float*)d_in[1];
    const float* Whh   = (const float*)d_in[2];
    const float* bih   = (const float*)d_in[3];
    const float* bhh   = (const float*)d_in[4];
    const float* Wout  = (const float*)d_in[5];
    const float* bout  = (const float*)d_in[6];
    const float* Wkey  = (const float*)d_in[7];
    const float* bkey  = (const float*)d_in[8];
    const float* alpha = (const float*)d_in[9];
    const float* gamma = (const float*)d_in[10];
    float* out = (float*)d_out;

    k_reset<<<32768, 256>>>();

    cudaLaunchAttribute a1, a2, a3, a4;

    for (int t = 0; t < TT; ++t) {
        const int sel = t & 1;

        {
            cudaLaunchConfig_t cfg = pdl_cfg(dim3(JGATE / 16), dim3(256), &a1);
            cudaLaunchKernelEx(&cfg, k_gates,
                               (const float*)(x_seq + (size_t)t * BB * INW),
                               Wih, Whh, bih, bhh, sel);
        }
        {
            cudaLaunchConfig_t cfg = pdl_cfg(dim3(8, 32), dim3(256), &a2);
            cudaLaunchKernelEx(&cfg, k_ok2, Wout, Wkey, bout, bkey,
                               (float*)out, t, sel);
        }
        {
            cudaLaunchConfig_t cfg = pdl_cfg(dim3(NCHUNK, BB), dim3(128), &a3);
            cudaLaunchKernelEx(&cfg, k_simup, alpha, t);
        }
        {
            cudaLaunchConfig_t cfg = pdl_cfg(dim3(16, BB), dim3(256), &a4);
            cudaLaunchKernelEx(&cfg, k_final, alpha, gamma, t);
        }
    }
}